// round 11
// baseline (speedup 1.0000x reference)
#include <cuda_runtime.h>
#include <cuda_fp16.h>
#include <float.h>

#define HDIM 384
#define TS   32
#define PS   48          // TS + 16 halo (rows/cols)
#define PSTR 49          // padded patch row stride
#define DHR  38          // Dh plane rows (patch rows 4..41)
#define DHSTR 33         // padded Dh row stride
#define HAR  47          // hA plane rows (patch rows 0..46)
#define HAC  41          // hA plane cols (patch cols 3..43, idx = col-3)
#define NTILE 12
#define NBLK (NTILE*NTILE*4)
#define PXB  1024        // pixels per block (32x32)

__device__ float g_partials[NBLK];
__device__ unsigned int g_count;   // zero-initialized
// D staging (fp16): [img(2)][block(576)][syi*10+sxi(100)][px(1024)] = 236 MB scratch
__device__ __half g_D[2u*NBLK*100u*PXB];

__device__ __forceinline__ float GX(int i){
    constexpr float t[7] = {0.32465246736f,0.60653065971f,0.88249690258f,1.0f,
                            0.88249690258f,0.60653065971f,0.32465246736f};
    return t[i];
}
__device__ __forceinline__ float GY(int i){
    constexpr float n = 0.039788735772973836f; // 1/(8*pi) = 1/(2*pi*sigma^2)
    constexpr float t[7] = {0.32465246736f*n,0.60653065971f*n,0.88249690258f*n,n,
                            0.88249690258f*n,0.60653065971f*n,0.32465246736f*n};
    return t[i];
}

// hA(r, c-3) = sum_i GX(i) * I[r][c-3+i]^2   (horizontal Gaussian of I^2)
__device__ __forceinline__ void build_hA(float* __restrict__ hA, const float* __restrict__ patch,
                                         int tid){
    for (int idx = tid; idx < HAR*HAC; idx += 256){
        int r = idx / HAC, cA = idx - r*HAC;
        const float* pr_ = patch + r*PSTR + cA;
        float s = 0.f;
        #pragma unroll
        for (int i = 0; i < 7; i++){ float v = pr_[i]; s = fmaf(GX(i)*v, v, s); }
        hA[idx] = s;
    }
}

// Half horizontal pass: 5 x-shifts at row shift syv.
// HALF=0 -> sxi 0..4 (sxv -5..-1), HALF=1 -> sxi 5..9 (sxv 0..4); plane p = sxi - 5*HALF.
// dh(p,hr,tx) = hA[R][tx+4] + hA[R-syv][tx+(HALF?4:9)-p+ (cA-space)] - 2*sum_i baseg[i]*win[i+4-p]
// where win[w] = patch[R-syv][tx + (HALF?0:5) + w]  (11-wide window).
template<int HALF>
__device__ __forceinline__ void compute_dh_half(float* __restrict__ dh, const float* __restrict__ patch,
                                                const float* __restrict__ hA,
                                                int syv, int tx, int ty){
    #pragma unroll
    for (int k = 0; k < 5; k++){
        int hr = ty + 8*k;
        if (hr < DHR){
            int R = hr + 4;
            const float* brow = patch + R*PSTR + tx;
            float baseg[7];
            #pragma unroll
            for (int i = 0; i < 7; i++) baseg[i] = GX(i) * brow[4 + i];
            float sa0 = hA[R*HAC + tx + 4];
            const float* wrow = patch + (R - syv)*PSTR + tx + (HALF ? 0 : 5);
            float win[11];
            #pragma unroll
            for (int w = 0; w < 11; w++) win[w] = wrow[w];
            const float* hrow = hA + (R - syv)*HAC + tx;
            #pragma unroll
            for (int p = 0; p < 5; p++){
                float cb = 0.f;
                #pragma unroll
                for (int i = 0; i < 7; i++)
                    cb = fmaf(baseg[i], win[i + 4 - p], cb);
                float hsh = hrow[(HALF ? 4 : 9) - p];
                dh[(p*DHR + hr)*DHSTR + tx] = fmaf(-2.f, cb, sa0 + hsh);
            }
        }
    }
}

// Vertical 7-tap sums over 5 planes for 4 CONSECUTIVE pixel rows (10-row shared window).
__device__ __forceinline__ void vertical5(const float* __restrict__ dh, float out[4][5],
                                          int tx, int prBase){
    #pragma unroll
    for (int p = 0; p < 5; p++){
        float w[10];
        #pragma unroll
        for (int j = 0; j < 10; j++) w[j] = dh[(p*DHR + prBase + j)*DHSTR + tx];
        #pragma unroll
        for (int q = 0; q < 4; q++){
            float d = 0.f;
            #pragma unroll
            for (int j = 0; j < 7; j++) d = fmaf(GY(j), w[q + j], d);
            out[q][p] = d;
        }
    }
}

// Consume one half: update dmin/vsum (exact fp32) AND stage fp16 D for phase 2.
template<int HALF>
__device__ __forceinline__ void consume_store5(const float* __restrict__ dh, int syv, int syi,
                                               float dmin[4], float vsum[4],
                                               int tx, int prBase, __half* __restrict__ gimg){
    float D[4][5];
    vertical5(dh, D, tx, prBase);
    #pragma unroll
    for (int q = 0; q < 4; q++){
        unsigned pxq = (unsigned)(prBase + q)*32u + (unsigned)tx;
        #pragma unroll
        for (int p = 0; p < 5; p++){
            int sxi = HALF*5 + p;
            int sxv = sxi - 5;
            float d = D[q][p];
            gimg[(unsigned)(syi*10 + sxi)*PXB + pxq] = __float2half(d);
            if (!(syv == 0 && sxv == 0)){
                dmin[q] = fminf(dmin[q], d);
                bool card = (syv == 0 && (sxv == 1 || sxv == -1)) ||
                            (sxv == 0 && (syv == 1 || syv == -1));
                if (card) vsum[q] += d;
            }
        }
    }
}

// Full phase-1 pipeline for one image: load patch, build hA, loop shifts in two halves.
__device__ __forceinline__ void process_image(const float* __restrict__ src,
                                              float* __restrict__ patch, float* __restrict__ hA,
                                              float* __restrict__ dh, __half* __restrict__ gimg,
                                              float dmin[4], float vsum[4],
                                              int p0r, int p0c, int tx, int ty, int tid, int prBase){
    for (int idx = tid; idx < PS*PS; idx += 256){
        int r = idx / PS, c = idx - r*PS;
        int gr = p0r - 7 + r; if (gr >= HDIM) gr -= HDIM;
        int gc = p0c - 7 + c; if (gc >= HDIM) gc -= HDIM;
        patch[r*PSTR + c] = src[gr*HDIM + gc];
    }
    __syncthreads();
    build_hA(hA, patch, tid);
    for (int syi = 0; syi < 10; syi++){
        int syv = syi - 5;
        __syncthreads();
        compute_dh_half<0>(dh, patch, hA, syv, tx, ty);
        __syncthreads();
        consume_store5<0>(dh, syv, syi, dmin, vsum, tx, prBase, gimg);
        __syncthreads();
        compute_dh_half<1>(dh, patch, hA, syv, tx, ty);
        __syncthreads();
        consume_store5<1>(dh, syv, syi, dmin, vsum, tx, prBase, gimg);
    }
    __syncthreads();
}

__global__ void __launch_bounds__(256, 4)
mind_loss_kernel(const float* __restrict__ pred, const float* __restrict__ gt,
                 float* __restrict__ out){
    extern __shared__ float smem[];
    float* patch = smem;                       // 2352
    float* hA    = smem + 2352;                // 1927 (47x41)
    float* dh    = smem + 4279;                // 6270 (5 planes of 38x33)
    __shared__ int lastFlag;

    int tid = threadIdx.x;
    int tx = tid & 31, ty = tid >> 5;
    int prBase = ty * 4;                       // 4 consecutive pixel rows per thread
    int b = blockIdx.z;
    int bid = (blockIdx.z*NTILE + blockIdx.y)*NTILE + blockIdx.x;
    int p0r = 7 + blockIdx.y * TS;             // global row of pixel pr==0 (patch local row 7)
    int p0c = 7 + blockIdx.x * TS;
    __half* gP = g_D + (unsigned)bid*100u*PXB;
    __half* gG = g_D + ((unsigned)(NBLK + bid))*100u*PXB;

    bool valid[4];
    bool colv = (p0c + tx) <= (HDIM - 1 - 7);
    #pragma unroll
    for (int q = 0; q < 4; q++)
        valid[q] = colv && ((p0r + prBase + q) <= (HDIM - 1 - 7));

    // -------- Phase 1: Dmin/Vsum + stage fp16 D, one image at a time --------
    float dminP[4], vsumP[4], dminG[4], vsumG[4];
    #pragma unroll
    for (int q = 0; q < 4; q++){ dminP[q] = FLT_MAX; vsumP[q] = 0.f; dminG[q] = FLT_MAX; vsumG[q] = 0.f; }

    process_image(pred + b*HDIM*HDIM, patch, hA, dh, gP, dminP, vsumP, p0r, p0c, tx, ty, tid, prBase);
    process_image(gt   + b*HDIM*HDIM, patch, hA, dh, gG, dminG, vsumG, p0r, p0c, tx, ty, tid, prBase);

    float invVP[4], invVG[4];
    #pragma unroll
    for (int q = 0; q < 4; q++){
        invVP[q] = 1.f / (vsumP[q]*0.25f + 1e-5f);
        invVG[q] = 1.f / (vsumG[q]*0.25f + 1e-5f);
    }

    // -------- Phase 2: stream staged fp16 D, accumulate |Mp - Mg| --------
    float acc = 0.f;
    for (int syi = 0; syi < 10; syi++){
        #pragma unroll
        for (int q = 0; q < 4; q++){
            if (!valid[q]) continue;
            unsigned pxq = (unsigned)(prBase + q)*32u + (unsigned)tx;
            const __half* bp = gP + (unsigned)(syi*10)*PXB + pxq;
            const __half* bg = gG + (unsigned)(syi*10)*PXB + pxq;
            float dP[10], dG[10];
            #pragma unroll
            for (int sxi = 0; sxi < 10; sxi++){
                dP[sxi] = __half2float(bp[(unsigned)sxi*PXB]);
                dG[sxi] = __half2float(bg[(unsigned)sxi*PXB]);
            }
            #pragma unroll
            for (int sxi = 0; sxi < 10; sxi++){
                if (!(syi == 5 && sxi == 5)){
                    float mp = __expf((dminP[q] - dP[sxi]) * invVP[q]);
                    float mg = __expf((dminG[q] - dG[sxi]) * invVG[q]);
                    acc += fabsf(mp - mg);
                }
            }
        }
    }

    // -------- Block reduction --------
    __syncthreads();
    dh[tid] = acc;
    __syncthreads();
    #pragma unroll
    for (int s = 128; s > 0; s >>= 1){
        if (tid < s) dh[tid] += dh[tid + s];
        __syncthreads();
    }
    if (tid == 0){
        g_partials[bid] = dh[0];
        __threadfence();
        unsigned int t = atomicAdd(&g_count, 1u);
        lastFlag = (t == NBLK - 1) ? 1 : 0;
    }
    __syncthreads();

    // -------- Last block: final reduction --------
    if (lastFlag){
        __threadfence();
        float s = 0.f;
        for (int i = tid; i < NBLK; i += 256) s += g_partials[i];
        dh[tid] = s;
        __syncthreads();
        #pragma unroll
        for (int k = 128; k > 0; k >>= 1){
            if (tid < k) dh[tid] += dh[tid + k];
            __syncthreads();
        }
        if (tid == 0){
            out[0] = dh[0] * (1.0f / 54212400.0f);  // 99*4*370*370
            atomicExch(&g_count, 0u);               // reset for next replay
        }
    }
}

extern "C" void kernel_launch(void* const* d_in, const int* in_sizes, int n_in,
                              void* d_out, int out_size){
    const float* pred = (const float*)d_in[0];
    const float* gt   = (const float*)d_in[1];
    float* out = (float*)d_out;

    cudaFuncSetAttribute(mind_loss_kernel, cudaFuncAttributeMaxDynamicSharedMemorySize, 42496);
    dim3 grid(NTILE, NTILE, 4);
    mind_loss_kernel<<<grid, 256, 42496>>>(pred, gt, out);
}

// round 15
// speedup vs baseline: 1.3427x; 1.3427x over previous
#include <cuda_runtime.h>
#include <cuda_fp16.h>
#include <float.h>

#define HDIM 384
#define TS   32
#define PSR  49          // patch rows (pixel pr at patch row pr+8; rows p0r-8 .. p0r+40)
#define PSC  48          // patch cols (pixel at col tx+7; cols p0c-7 .. p0c+40)
#define PSTR 49          // padded patch row stride
#define DHR  38          // dh plane rows (patch rows 5..42)
#define DHSTR 33         // padded dh row stride
#define NSX  10          // s_x plane count (sxv = sxi - 5)
#define HAR  49          // hA plane rows (patch rows 0..48)
#define HAC  41          // hA/A plane cols (patch cols 3..43, idx = col-3)
#define NTILE 12
#define NBLK (NTILE*NTILE*4)
#define PXB  1024        // pixels per block (32x32)

__device__ float g_partials[NBLK];
__device__ unsigned int g_count;   // zero-initialized
// D staging (fp16, sxi-pairs packed in half2): [img(2)][block(576)][syi*5+pair(50)][px(1024)]
__device__ __half2 g_D[2u*NBLK*50u*PXB];

__device__ __forceinline__ float GX(int i){
    constexpr float t[7] = {0.32465246736f,0.60653065971f,0.88249690258f,1.0f,
                            0.88249690258f,0.60653065971f,0.32465246736f};
    return t[i];
}
__device__ __forceinline__ float GY(int i){
    constexpr float n = 0.039788735772973836f; // 1/(8*pi) = 1/(2*pi*sigma^2)
    constexpr float t[7] = {0.32465246736f*n,0.60653065971f*n,0.88249690258f*n,n,
                            0.88249690258f*n,0.60653065971f*n,0.32465246736f*n};
    return t[i];
}

// hA(r, c-3) = sum_i GX(i) * I[r][c-3+i]^2   (horizontal Gaussian of I^2), rows 0..48
__device__ __forceinline__ void build_hA(float* __restrict__ hA, const float* __restrict__ patch,
                                         int tid){
    for (int idx = tid; idx < HAR*HAC; idx += 256){
        int r = idx / HAC, cA = idx - r*HAC;
        const float* pr_ = patch + r*PSTR + cA;
        float s = 0.f;
        #pragma unroll
        for (int i = 0; i < 7; i++){ float v = pr_[i]; s = fmaf(GX(i)*v, v, s); }
        hA[idx] = s;
    }
}

// A(r, cA) = sum_j GY(j) * hA[r-3+j][cA], valid rows r in 3..44 (needs hA rows 0..47)
__device__ __forceinline__ void build_A(float* __restrict__ A, const float* __restrict__ hA,
                                        int tid){
    for (int idx = tid; idx < HAR*HAC; idx += 256){
        int r = idx / HAC, cA = idx - r*HAC;
        if (r >= 3 && r <= 44){
            const float* h0 = hA + (r - 3)*HAC + cA;
            float s = 0.f;
            #pragma unroll
            for (int j = 0; j < 7; j++) s = fmaf(GY(j), h0[j*HAC], s);
            A[idx] = s;
        }
    }
}

// Cross-term horizontal pass for ALL 10 x-shifts at row shift syv:
//   dh(sxi,hr,tx) = sum_i GX(i)*I[R][tx+4+i]*I[R-syv][tx+9-sxi+i],  R = hr+5
__device__ __forceinline__ void compute_cb_all(float* __restrict__ dh, const float* __restrict__ patch,
                                               int syv, int tx, int ty){
    #pragma unroll
    for (int k = 0; k < 5; k++){
        int hr = ty + 8*k;
        if (hr < DHR){
            int R = hr + 5;
            const float* brow = patch + R*PSTR + tx;
            float baseg[7];
            #pragma unroll
            for (int i = 0; i < 7; i++) baseg[i] = GX(i) * brow[4 + i];
            const float* wrow = patch + (R - syv)*PSTR + tx;
            float win[16];
            #pragma unroll
            for (int w = 0; w < 16; w++) win[w] = wrow[w];
            #pragma unroll
            for (int sxi = 0; sxi < NSX; sxi++){
                float cb = 0.f;
                #pragma unroll
                for (int i = 0; i < 7; i++)
                    cb = fmaf(baseg[i], win[i + 9 - sxi], cb);
                dh[(sxi*DHR + hr)*DHSTR + tx] = cb;
            }
        }
    }
}

// Vertical 7-tap cross sums for 4 CONSECUTIVE pixel rows prBase..prBase+3 (10-row window).
__device__ __forceinline__ void vertical_all(const float* __restrict__ dh, float out[4][NSX],
                                             int tx, int prBase){
    #pragma unroll
    for (int sxi = 0; sxi < NSX; sxi++){
        float w[10];
        #pragma unroll
        for (int j = 0; j < 10; j++) w[j] = dh[(sxi*DHR + prBase + j)*DHSTR + tx];
        #pragma unroll
        for (int q = 0; q < 4; q++){
            float d = 0.f;
            #pragma unroll
            for (int j = 0; j < 7; j++) d = fmaf(GY(j), w[q + j], d);
            out[q][sxi] = d;
        }
    }
}

// Consume one syv: D = A(p) + A(p-s) - 2*vcb; update dmin/vsum (fp32) + stage packed fp16.
__device__ __forceinline__ void consume_store(const float* __restrict__ dh,
                                              const float* __restrict__ A,
                                              int syv, int syi,
                                              float dmin[4], float vsum[4],
                                              int tx, int prBase, __half2* __restrict__ gimg){
    float Vc[4][NSX];
    vertical_all(dh, Vc, tx, prBase);
    float D[4][NSX];
    #pragma unroll
    for (int q = 0; q < 4; q++){
        float a0 = A[(prBase + q + 8)*HAC + tx + 4];
        const float* ash = A + (prBase + q + 8 - syv)*HAC + tx;
        #pragma unroll
        for (int sxi = 0; sxi < NSX; sxi++){
            float d = fmaf(-2.f, Vc[q][sxi], a0 + ash[9 - sxi]);
            D[q][sxi] = d;
            int sxv = sxi - 5;
            if (!(syv == 0 && sxv == 0)){
                dmin[q] = fminf(dmin[q], d);
                bool card = (syv == 0 && (sxv == 1 || sxv == -1)) ||
                            (sxv == 0 && (syv == 1 || syv == -1));
                if (card) vsum[q] += d;
            }
        }
        unsigned pxq = (unsigned)(prBase + q)*32u + (unsigned)tx;
        #pragma unroll
        for (int pair = 0; pair < 5; pair++)
            gimg[(unsigned)(syi*5 + pair)*PXB + pxq] =
                __floats2half2_rn(D[q][2*pair], D[q][2*pair + 1]);
    }
}

// Full phase-1 pipeline for one image.
__device__ __forceinline__ void process_image(const float* __restrict__ src,
                                              float* __restrict__ patch, float* __restrict__ A,
                                              float* __restrict__ dh, __half2* __restrict__ gimg,
                                              float dmin[4], float vsum[4],
                                              int p0r, int p0c, int tx, int ty, int tid, int prBase){
    for (int idx = tid; idx < PSR*PSC; idx += 256){
        int r = idx / PSC, c = idx - r*PSC;
        int gr = p0r - 8 + r; if (gr < 0) gr += HDIM; if (gr >= HDIM) gr -= HDIM;
        int gc = p0c - 7 + c; if (gc >= HDIM) gc -= HDIM;
        patch[r*PSTR + c] = src[gr*HDIM + gc];
    }
    __syncthreads();
    build_hA(dh, patch, tid);          // hA scratch overlaid on dh buffer
    __syncthreads();
    build_A(A, dh, tid);
    for (int syi = 0; syi < 10; syi++){
        int syv = syi - 5;
        __syncthreads();
        compute_cb_all(dh, patch, syv, tx, ty);
        __syncthreads();
        consume_store(dh, A, syv, syi, dmin, vsum, tx, prBase, gimg);
    }
    __syncthreads();
}

__global__ void __launch_bounds__(256, 3)
mind_loss_kernel(const float* __restrict__ pred, const float* __restrict__ gt,
                 float* __restrict__ out){
    extern __shared__ float smem[];
    float* patch = smem;                       // 49x49 = 2401
    float* A     = smem + 2401;                // 49x41 = 2009
    float* dh    = smem + 4410;                // 12540 (10 planes of 38x33); hA scratch overlays
    __shared__ int lastFlag;

    int tid = threadIdx.x;
    int tx = tid & 31, ty = tid >> 5;
    int prBase = ty * 4;                       // 4 consecutive pixel rows per thread
    int b = blockIdx.z;
    int bid = (blockIdx.z*NTILE + blockIdx.y)*NTILE + blockIdx.x;
    int p0r = 7 + blockIdx.y * TS;             // global row of pixel pr==0
    int p0c = 7 + blockIdx.x * TS;
    __half2* gP = g_D + (unsigned)bid*50u*PXB;
    __half2* gG = g_D + ((unsigned)(NBLK + bid))*50u*PXB;

    bool valid[4];
    bool colv = (p0c + tx) <= (HDIM - 1 - 7);
    #pragma unroll
    for (int q = 0; q < 4; q++)
        valid[q] = colv && ((p0r + prBase + q) <= (HDIM - 1 - 7));

    // -------- Phase 1: Dmin/Vsum + stage packed D, one image at a time --------
    float dminP[4], vsumP[4], dminG[4], vsumG[4];
    #pragma unroll
    for (int q = 0; q < 4; q++){ dminP[q] = FLT_MAX; vsumP[q] = 0.f; dminG[q] = FLT_MAX; vsumG[q] = 0.f; }

    process_image(pred + b*HDIM*HDIM, patch, A, dh, gP, dminP, vsumP, p0r, p0c, tx, ty, tid, prBase);
    process_image(gt   + b*HDIM*HDIM, patch, A, dh, gG, dminG, vsumG, p0r, p0c, tx, ty, tid, prBase);

    float invVP[4], invVG[4];
    #pragma unroll
    for (int q = 0; q < 4; q++){
        invVP[q] = 1.f / (vsumP[q]*0.25f + 1e-5f);
        invVG[q] = 1.f / (vsumG[q]*0.25f + 1e-5f);
    }

    // -------- Phase 2: stream staged half2 D, accumulate |Mp - Mg| --------
    float acc = 0.f;
    for (int syi = 0; syi < 10; syi++){
        #pragma unroll
        for (int q = 0; q < 4; q++){
            if (!valid[q]) continue;
            unsigned pxq = (unsigned)(prBase + q)*32u + (unsigned)tx;
            __half2 hp[5], hg[5];
            #pragma unroll
            for (int pair = 0; pair < 5; pair++){
                unsigned off = (unsigned)(syi*5 + pair)*PXB + pxq;
                hp[pair] = gP[off];
                hg[pair] = gG[off];
            }
            #pragma unroll
            for (int sxi = 0; sxi < NSX; sxi++){
                if (!(syi == 5 && sxi == 5)){
                    float2 fp = __half22float2(hp[sxi >> 1]);
                    float2 fg = __half22float2(hg[sxi >> 1]);
                    float dPv = (sxi & 1) ? fp.y : fp.x;
                    float dGv = (sxi & 1) ? fg.y : fg.x;
                    float mp = __expf((dminP[q] - dPv) * invVP[q]);
                    float mg = __expf((dminG[q] - dGv) * invVG[q]);
                    acc += fabsf(mp - mg);
                }
            }
        }
    }

    // -------- Block reduction --------
    __syncthreads();
    dh[tid] = acc;
    __syncthreads();
    #pragma unroll
    for (int s = 128; s > 0; s >>= 1){
        if (tid < s) dh[tid] += dh[tid + s];
        __syncthreads();
    }
    if (tid == 0){
        g_partials[bid] = dh[0];
        __threadfence();
        unsigned int t = atomicAdd(&g_count, 1u);
        lastFlag = (t == NBLK - 1) ? 1 : 0;
    }
    __syncthreads();

    // -------- Last block: final reduction --------
    if (lastFlag){
        __threadfence();
        float s = 0.f;
        for (int i = tid; i < NBLK; i += 256) s += g_partials[i];
        dh[tid] = s;
        __syncthreads();
        #pragma unroll
        for (int k = 128; k > 0; k >>= 1){
            if (tid < k) dh[tid] += dh[tid + k];
            __syncthreads();
        }
        if (tid == 0){
            out[0] = dh[0] * (1.0f / 54212400.0f);  // 99*4*370*370
            atomicExch(&g_count, 0u);               // reset for next replay
        }
    }
}

extern "C" void kernel_launch(void* const* d_in, const int* in_sizes, int n_in,
                              void* d_out, int out_size){
    const float* pred = (const float*)d_in[0];
    const float* gt   = (const float*)d_in[1];
    float* out = (float*)d_out;

    cudaFuncSetAttribute(mind_loss_kernel, cudaFuncAttributeMaxDynamicSharedMemorySize, 68608);
    dim3 grid(NTILE, NTILE, 4);
    mind_loss_kernel<<<grid, 256, 68608>>>(pred, gt, out);
}